// round 6
// baseline (speedup 1.0000x reference)
#include <cuda_runtime.h>
#include <cstdint>

// Problem constants
#define BATCH   256
#define UNITS   256
#define DZ      128
#define DX      128
#define TSTEPS  1024
#define NG      1024   // 4*UNITS gate columns
#define KTOT    512    // z(128) + x(128) + h(256)

#define NCTA    128
#define NTHR    512

// ---------------- persistent device state ----------------
__device__ float g_H[2][BATCH * UNITS];   // hidden state, double-buffered
__device__ float g_Z[BATCH * DZ];         // sampled latent for next step

// software grid barrier (sense-reversing generation counter)
__device__ volatile unsigned g_gen = 0;
__device__ unsigned          g_cnt = 0;

__device__ __forceinline__ void grid_sync() {
    __syncthreads();
    if (threadIdx.x == 0) {
        __threadfence();                      // release my CTA's writes (L2)
        unsigned gen = g_gen;
        if (atomicAdd(&g_cnt, 1u) == NCTA - 1) {
            g_cnt = 0;
            __threadfence();
            g_gen = gen + 1;                  // publish
        } else {
            while (g_gen == gen) { __nanosleep(64); }
        }
        __threadfence();                      // acquire
    }
    __syncthreads();
}

// ---------------- packed f32x2 helpers ----------------
__device__ __forceinline__ unsigned long long pack2(float x, float y) {
    unsigned long long r;
    asm("mov.b64 %0, {%1, %2};" : "=l"(r) : "f"(x), "f"(y));
    return r;
}
__device__ __forceinline__ void unpack2(unsigned long long v, float& x, float& y) {
    asm("mov.b64 {%0, %1}, %2;" : "=f"(x), "=f"(y) : "l"(v));
}
__device__ __forceinline__ void ffma2(unsigned long long& d, unsigned long long a,
                                      unsigned long long b) {
    asm("fma.rn.f32x2 %0, %1, %2, %0;" : "+l"(d) : "l"(a), "l"(b));
}

__device__ __forceinline__ float ld_cg(const float* p) {
    float v; asm volatile("ld.global.cg.f32 %0, [%1];" : "=f"(v) : "l"(p)); return v;
}
__device__ __forceinline__ void st_cg(float* p, float v) {
    asm volatile("st.global.cg.f32 [%0], %1;" :: "l"(p), "f"(v));
}

__device__ __forceinline__ float sigmoidf_acc(float x) {
    return 1.0f / (1.0f + expf(-x));
}

// SMEM layout (floats):
//   [0, 32768)            Wg   : gate weights  [512][64]   (persistent)
//   [32768, 34848)        W2   : head weights  [8][260]    (persistent, padded)
//   [34848, 34848+16512)  SH   : phase1 s-tile [32][512] / phase2 h-tile [64][258]
//   [.. +256)             EXm  : mu exchange   [64][4]
//   [.. +256)             EXs  : sigma exchange[64][4]
#define SM_W2    32768
#define SM_SH    34848
#define SM_EXM   (SM_SH + 16512)
#define SM_EXS   (SM_EXM + 256)
#define SM_FLOATS (SM_EXS + 256)           // 51616 floats = 206464 bytes

__global__ void __launch_bounds__(NTHR, 1) fused_lstm_persistent(
    const float* __restrict__ inputs,   // [B, T, DX]
    const float* __restrict__ Wk,       // [256, 1024]
    const float* __restrict__ Wr,       // [256, 1024]
    const float* __restrict__ bias,     // [1024]
    const float* __restrict__ Wmu,      // [256, 128]
    const float* __restrict__ bmu,      // [128]
    const float* __restrict__ Wsg,      // [256, 128]
    const float* __restrict__ bsg,      // [128]
    const float* __restrict__ eps,      // [T-1, B, DZ]
    float* __restrict__ out)            // mu [B,T,DZ] ++ sigma [B,T,DZ]
{
    extern __shared__ float sm[];
    float* Wg  = sm;
    float* W2  = sm + SM_W2;
    float* SH  = sm + SM_SH;
    float* EXm = sm + SM_EXM;
    float* EXs = sm + SM_EXS;

    const int tid = threadIdx.x;
    const int cta = blockIdx.x;

    // ---- phase-1 identity: CTA = (bg, ug) -> 32 batch x 16 units ----
    const int ug = cta & 15,  bg = cta >> 4;
    const int u  = tid & 15,  b  = tid >> 4;
    const int u0 = ug * 16,   b0 = bg * 32;

    // ---- phase-2 identity: CTA = (bg2, og) -> 64 batch x (4 mu + 4 sigma cols) ----
    const int bg2 = cta >> 5, og = cta & 31;
    const int bl2 = tid >> 3, j2 = tid & 7;
    const int zc2 = og * 4 + (j2 & 3);
    const bool is_sig = (j2 >= 4);
    const int b2 = bg2 * 64 + bl2;

    // ---- one-time: stage persistent weight tiles into SMEM ----
    #pragma unroll
    for (int g = 0; g < 4; ++g) {
        #pragma unroll 4
        for (int rep = 0; rep < 16; ++rep) {
            const int k  = rep * 32 + (tid >> 4);
            const int uu = tid & 15;
            const float* src = (k < 256) ? (Wk + (size_t)k * NG)
                                         : (Wr + (size_t)(k - 256) * NG);
            Wg[k * 64 + uu * 4 + g] = src[g * 256 + u0 + uu];
        }
    }
    for (int i = tid; i < 8 * 256; i += NTHR) {
        const int jj = i >> 8, k = i & 255;
        const int zc = og * 4 + (jj & 3);
        W2[jj * 260 + k] = (jj < 4) ? Wmu[(size_t)k * DZ + zc]
                                    : Wsg[(size_t)k * DZ + zc];
    }

    // per-thread constants held in registers for the whole run
    const float b_i = bias[u0 + u];
    const float b_f = bias[256 + u0 + u];
    const float b_g = bias[512 + u0 + u];
    const float b_o = bias[768 + u0 + u];
    const float bh  = is_sig ? bsg[zc2] : bmu[zc2];
    const int   hidx = (b0 + b) * UNITS + (u0 + u);
    float c_reg = 0.0f;   // cell state: thread-exclusive -> register resident

    // ---- zero initial state (h0, z0) ----
    for (int i = cta * NTHR + tid; i < BATCH * UNITS; i += NCTA * NTHR) g_H[0][i] = 0.0f;
    for (int i = cta * NTHR + tid; i < BATCH * DZ;    i += NCTA * NTHR) g_Z[i]    = 0.0f;

    grid_sync();

    for (int t = 0; t < TSTEPS; ++t) {
        const float* __restrict__ Hin  = g_H[t & 1];
        float* __restrict__       Hout = g_H[(t & 1) ^ 1];

        // ================= PHASE 1: gates GEMM + LSTM update =================
        // stage s = [z | x_t | h] for this CTA's 32 batch rows (col = tid)
        {
            const int col = tid;
            if (col < 128) {
                #pragma unroll 8
                for (int r = 0; r < 32; ++r)
                    SH[r * 512 + col] = ld_cg(&g_Z[(b0 + r) * DZ + col]);
            } else if (col < 256) {
                const float* xp = inputs + (size_t)t * DX + (col - 128);
                #pragma unroll 8
                for (int r = 0; r < 32; ++r)
                    SH[r * 512 + col] = __ldg(xp + (size_t)(b0 + r) * (TSTEPS * DX));
            } else {
                #pragma unroll 8
                for (int r = 0; r < 32; ++r)
                    SH[r * 512 + col] = ld_cg(&Hin[(b0 + r) * UNITS + (col - 256)]);
            }
        }
        __syncthreads();

        unsigned long long acc_if = 0ULL, acc_go = 0ULL;
        {
            const float* srow = SH + b * 512;
            const float* wcol = Wg + u * 4;
            #pragma unroll 4
            for (int k4 = 0; k4 < 512; k4 += 4) {
                const float4 sv = *reinterpret_cast<const float4*>(srow + k4);
                {
                    const ulonglong2 wp = *reinterpret_cast<const ulonglong2*>(wcol + (k4 + 0) * 64);
                    const unsigned long long s2 = pack2(sv.x, sv.x);
                    ffma2(acc_if, s2, wp.x); ffma2(acc_go, s2, wp.y);
                }
                {
                    const ulonglong2 wp = *reinterpret_cast<const ulonglong2*>(wcol + (k4 + 1) * 64);
                    const unsigned long long s2 = pack2(sv.y, sv.y);
                    ffma2(acc_if, s2, wp.x); ffma2(acc_go, s2, wp.y);
                }
                {
                    const ulonglong2 wp = *reinterpret_cast<const ulonglong2*>(wcol + (k4 + 2) * 64);
                    const unsigned long long s2 = pack2(sv.z, sv.z);
                    ffma2(acc_if, s2, wp.x); ffma2(acc_go, s2, wp.y);
                }
                {
                    const ulonglong2 wp = *reinterpret_cast<const ulonglong2*>(wcol + (k4 + 3) * 64);
                    const unsigned long long s2 = pack2(sv.w, sv.w);
                    ffma2(acc_if, s2, wp.x); ffma2(acc_go, s2, wp.y);
                }
            }
        }

        float iv, fv, gv, ov;
        unpack2(acc_if, iv, fv);
        unpack2(acc_go, gv, ov);
        iv += b_i; fv += b_f; gv += b_g; ov += b_o;

        const float is_g = sigmoidf_acc(iv);
        const float fs_g = sigmoidf_acc(fv);
        const float gt_g = tanhf(gv);
        const float os_g = sigmoidf_acc(ov);
        c_reg = fs_g * c_reg + is_g * gt_g;
        st_cg(&Hout[hidx], os_g * tanhf(c_reg));

        grid_sync();   // h_{t+1} visible chip-wide

        // ================= PHASE 2: heads + sample + output =================
        // stage h tile: 64 rows x 256 cols (padded rows of 258)
        {
            const int col = tid & 255;
            const int r0  = tid >> 8;          // 0 or 1
            #pragma unroll 8
            for (int r = r0; r < 64; r += 2)
                SH[r * 258 + col] = ld_cg(&Hout[(bg2 * 64 + r) * UNITS + col]);
        }
        __syncthreads();

        unsigned long long acc2 = 0ULL;
        {
            const float* hrow  = SH + bl2 * 258;
            const float* w2row = W2 + j2 * 260;
            #pragma unroll 8
            for (int k = 0; k < 256; k += 2) {
                const unsigned long long hp =
                    *reinterpret_cast<const unsigned long long*>(hrow + k);
                const unsigned long long wp =
                    *reinterpret_cast<const unsigned long long*>(w2row + k);
                ffma2(acc2, hp, wp);
            }
        }
        float lo, hi;
        unpack2(acc2, lo, hi);
        float val = lo + hi + bh;
        if (is_sig)
            val = fmaxf(val, 0.0f) + log1pf(expf(-fabsf(val))) + 1e-6f;  // softplus + 1e-6

        const size_t obase = (size_t)b2 * (TSTEPS * DZ) + (size_t)t * DZ + zc2;
        if (is_sig) out[(size_t)BATCH * TSTEPS * DZ + obase] = val;
        else        out[obase] = val;

        // exchange mu/sigma inside the CTA, then sample z for step t+1
        if (is_sig) EXs[bl2 * 4 + (j2 & 3)] = val;
        else        EXm[bl2 * 4 + (j2 & 3)] = val;
        __syncthreads();
        if (!is_sig && t < TSTEPS - 1) {
            const float sg = EXs[bl2 * 4 + j2];
            const float e  = __ldg(&eps[(size_t)t * (BATCH * DZ) + (size_t)b2 * DZ + zc2]);
            st_cg(&g_Z[b2 * DZ + zc2], fmaf(sg, e, val));
        }

        grid_sync();   // z_{t+1} visible before next phase 1
    }
}

extern "C" void kernel_launch(void* const* d_in, const int* in_sizes, int n_in,
                              void* d_out, int out_size) {
    (void)in_sizes; (void)n_in; (void)out_size;
    const float* inputs = (const float*)d_in[0];
    const float* Wk     = (const float*)d_in[1];
    const float* Wr     = (const float*)d_in[2];
    const float* bias   = (const float*)d_in[3];
    const float* Wmu    = (const float*)d_in[4];
    const float* bmu    = (const float*)d_in[5];
    const float* Wsg    = (const float*)d_in[6];
    const float* bsg    = (const float*)d_in[7];
    const float* eps    = (const float*)d_in[8];
    float* out          = (float*)d_out;

    const size_t smem_bytes = (size_t)SM_FLOATS * sizeof(float);  // 206464 B
    cudaFuncSetAttribute(fused_lstm_persistent,
                         cudaFuncAttributeMaxDynamicSharedMemorySize,
                         (int)smem_bytes);

    fused_lstm_persistent<<<NCTA, NTHR, smem_bytes>>>(
        inputs, Wk, Wr, bias, Wmu, bmu, Wsg, bsg, eps, out);
}

// round 9
// speedup vs baseline: 1.6778x; 1.6778x over previous
#include <cuda_runtime.h>
#include <cstdint>

// Problem constants
#define BATCH   256
#define UNITS   256
#define DZ      128
#define DX      128
#define TST     1024
#define NG      1024   // 4*UNITS gate columns
#define KTOT    512    // z(128) + x(128) + h(256)

#define NCTA    128
#define NTHR    512
#define CPG     16     // CTAs per batch group
#define NGRP    8      // batch groups
#define GB      32     // batch rows per group

// ---------------- persistent device state ----------------
__device__ float g_H[2][BATCH * UNITS];
__device__ float g_Z[BATCH * DZ];
__device__ unsigned          g_cnt[NGRP * 32];   // padded to 128B per group
__device__ volatile unsigned g_gen[NGRP * 32];
__device__ unsigned          g_done[NGRP * 32];

// ---------------- packed f32x2 helpers ----------------
typedef unsigned long long ull;
__device__ __forceinline__ ull pack2(float x, float y) {
    ull r; asm("mov.b64 %0, {%1, %2};" : "=l"(r) : "f"(x), "f"(y)); return r;
}
__device__ __forceinline__ void unpack2(ull v, float& x, float& y) {
    asm("mov.b64 {%0, %1}, %2;" : "=f"(x), "=f"(y) : "l"(v));
}
__device__ __forceinline__ void ffma2(ull& d, ull a, ull b) {
    asm("fma.rn.f32x2 %0, %1, %2, %0;" : "+l"(d) : "l"(a), "l"(b));
}
__device__ __forceinline__ void fadd2(ull& d, ull a) {
    asm("add.rn.f32x2 %0, %0, %1;" : "+l"(d) : "l"(a));
}
__device__ __forceinline__ float ld_cg(const float* p) {
    float v; asm volatile("ld.global.cg.f32 %0, [%1];" : "=f"(v) : "l"(p)); return v;
}
__device__ __forceinline__ void st_cg(float* p, float v) {
    asm volatile("st.global.cg.f32 [%0], %1;" :: "l"(p), "f"(v));
}
__device__ __forceinline__ float sigmoidf_acc(float x) {
    return 1.0f / (1.0f + expf(-x));
}

// ---------------- group barrier (16 CTAs, monotonic target) ----------------
__device__ __forceinline__ void group_sync(int grp, unsigned target) {
    __syncthreads();
    if (threadIdx.x == 0) {
        __threadfence();
        unsigned a = atomicAdd(&g_cnt[grp * 32], 1u) + 1u;
        if (a == (unsigned)CPG * target) {
            __threadfence();
            g_gen[grp * 32] = target;
        } else {
            while (g_gen[grp * 32] < target) { }
        }
        __threadfence();
    }
    __syncthreads();
}

// SMEM layout (floats):
//   Wg : [512][64]   gate weights, persistent         @ 0       (32768)
//   W2 : [16][260]   head weights, persistent         @ 32768   (4160)
//   S  : [512][36]   s-tile (transposed) / partials / h-tile  @ 36928 (18432)
//   EX : [32][8]     sigma exchange                   @ 55360   (256)
#define WG_OFF 0
#define W2_OFF 32768
#define S_OFF  36928
#define EX_OFF 55360
#define SM_FLOATS 55616           // 222464 bytes

__global__ void __launch_bounds__(NTHR, 1) fused_lstm_persistent(
    const float* __restrict__ inputs,   // [B, T, DX]
    const float* __restrict__ Wk,       // [256, 1024]
    const float* __restrict__ Wr,       // [256, 1024]
    const float* __restrict__ bias,     // [1024]
    const float* __restrict__ Wmu,      // [256, 128]
    const float* __restrict__ bmu,      // [128]
    const float* __restrict__ Wsg,      // [256, 128]
    const float* __restrict__ bsg,      // [128]
    const float* __restrict__ eps,      // [T-1, B, DZ]
    float* __restrict__ out)            // mu [B,T,DZ] ++ sigma [B,T,DZ]
{
    extern __shared__ float sm[];
    float* Wg = sm + WG_OFF;
    float* W2 = sm + W2_OFF;
    float* S  = sm + S_OFF;
    float* EX = sm + EX_OFF;

    const int tid = threadIdx.x;
    const int cta = blockIdx.x;
    const int grp = cta >> 4;          // batch group 0..7
    const int cg  = cta & 15;          // CTA index within group
    const int gb0 = grp * GB;          // first batch row of group
    const int u0  = cg * 16;           // first unit of this CTA's gate slice

    // ---- one-time staging: gate weights [k][u*4+g] ----
    for (int i = tid; i < 512 * 16; i += NTHR) {
        const int k = i >> 4, uu = i & 15;
        const float* src = (k < 256) ? (Wk + (size_t)k * NG)
                                     : (Wr + (size_t)(k - 256) * NG);
        #pragma unroll
        for (int g = 0; g < 4; ++g)
            Wg[k * 64 + uu * 4 + g] = src[g * 256 + u0 + uu];
    }
    // ---- one-time staging: head weights, rows r=(j*2+head), cols k ----
    for (int i = tid; i < 16 * 256; i += NTHR) {
        const int r = i >> 8, k = i & 255;
        const int j = r >> 1, head = r & 1;
        const int zc = cg * 8 + j;
        W2[r * 260 + k] = head ? Wsg[(size_t)k * DZ + zc]
                               : Wmu[(size_t)k * DZ + zc];
    }
    // ---- zero initial state for this group's rows ----
    g_H[0][gb0 * UNITS + cg * 512 + tid] = 0.0f;        // 16*512 = 32*256
    if (tid < 256) g_Z[gb0 * DZ + cg * 256 + tid] = 0.0f;

    // ---- phase-1 mainloop identity: warp = (ks, upart); lane = (uu, bg) ----
    const int warp = tid >> 5, lane = tid & 31;
    const int ks     = warp >> 1;                 // k-split 0..7 (64 k each)
    const int ulocal = (warp & 1) * 8 + ((lane >> 2) & 7);
    const int b8     = (lane & 3) * 8;            // first of 8 batch rows
    const int k0     = ks * 64;

    // ---- reducer identity (tid < 256): owns (b-pair rbp, unit ru) ----
    const int rbp = tid >> 4;                     // 0..15 b-pairs
    const int ru  = tid & 15;
    const int rug = u0 + ru;
    float bi = 0.f, bf = 0.f, bg_ = 0.f, bo = 0.f;
    if (tid < 256) {
        bi  = bias[rug];       bf = bias[256 + rug];
        bg_ = bias[512 + rug]; bo = bias[768 + rug];
    }
    // partner base for k-split reduction: partner(ks) layout in partials
    const int partner0 = ((ru >> 3) * 32) + ((ru & 7) * 4) + (rbp >> 2);
    const float* rbase = S + partner0 * 36 + (rbp & 3) * 8;
    float c0 = 0.0f, c1 = 0.0f;                   // cell state (register resident)

    // ---- phase-2 identity: thread = (pb, pj, ph) ----
    const int pb  = tid >> 4;                     // 0..31 batch row in group
    const int pj  = (tid >> 1) & 7;               // z-col within CTA slice
    const int ph  = tid & 1;                      // 0 = mu, 1 = sigma
    const int prow = (pj << 1) | ph;
    const int pzc  = cg * 8 + pj;                 // global z column
    const float bh = ph ? bsg[pzc] : bmu[pzc];
    const int pbg  = gb0 + pb;

    unsigned nbar = 0;
    group_sync(grp, ++nbar);

    for (int t = 0; t < TST; ++t) {
        const float* __restrict__ Hin  = g_H[t & 1];
        float* __restrict__       Hout = g_H[(t & 1) ^ 1];

        // ============ PHASE 1a: stage s = [z|x|h] transposed S[k][b] ============
        {
            const int k = tid;
            float* dst = S + k * 36;
            if (k < 128) {
                const float* zsrc = g_Z + gb0 * DZ + k;
                #pragma unroll 8
                for (int r = 0; r < 32; ++r) dst[r] = ld_cg(zsrc + r * DZ);
            } else if (k < 256) {
                const float* xsrc = inputs + (size_t)gb0 * (TST * DX)
                                           + (size_t)t * DX + (k - 128);
                #pragma unroll 8
                for (int r = 0; r < 32; ++r)
                    dst[r] = __ldg(xsrc + (size_t)r * (TST * DX));
            } else {
                const float* hsrc = Hin + gb0 * UNITS + (k - 256);
                #pragma unroll 8
                for (int r = 0; r < 32; ++r) dst[r] = ld_cg(hsrc + r * UNITS);
            }
        }
        __syncthreads();

        // ============ PHASE 1b: register-blocked gates GEMM (8b x 4g x 64k) =====
        ull a[16];
        #pragma unroll
        for (int i = 0; i < 16; ++i) a[i] = 0ULL;
        {
            const float* wptr = Wg + k0 * 64 + ulocal * 4;
            const float* sptr = S + k0 * 36 + b8;
            #pragma unroll 2
            for (int kk = 0; kk < 64; ++kk) {
                const float4 w4 = *reinterpret_cast<const float4*>(wptr);
                const ulonglong2 sA = *reinterpret_cast<const ulonglong2*>(sptr);
                const ulonglong2 sB = *reinterpret_cast<const ulonglong2*>(sptr + 4);
                wptr += 64; sptr += 36;
                const ull d0 = pack2(w4.x, w4.x);
                const ull d1 = pack2(w4.y, w4.y);
                const ull d2 = pack2(w4.z, w4.z);
                const ull d3 = pack2(w4.w, w4.w);
                ffma2(a[0],  sA.x, d0); ffma2(a[1],  sA.x, d1);
                ffma2(a[2],  sA.x, d2); ffma2(a[3],  sA.x, d3);
                ffma2(a[4],  sA.y, d0); ffma2(a[5],  sA.y, d1);
                ffma2(a[6],  sA.y, d2); ffma2(a[7],  sA.y, d3);
                ffma2(a[8],  sB.x, d0); ffma2(a[9],  sB.x, d1);
                ffma2(a[10], sB.x, d2); ffma2(a[11], sB.x, d3);
                ffma2(a[12], sB.y, d0); ffma2(a[13], sB.y, d1);
                ffma2(a[14], sB.y, d2); ffma2(a[15], sB.y, d3);
            }
        }
        __syncthreads();     // all S reads done -> reuse region for partials

        // write partials: 16 u64 per thread at stride 36 floats
        {
            float* dst = S + tid * 36;
            #pragma unroll
            for (int i = 0; i < 8; ++i) {
                ulonglong2 v; v.x = a[2 * i]; v.y = a[2 * i + 1];
                *reinterpret_cast<ulonglong2*>(dst + i * 4) = v;
            }
        }
        __syncthreads();

        // ============ PHASE 1c: K-split reduction + LSTM update (tid<256) ======
        if (tid < 256) {
            ull r0 = 0ULL, r1 = 0ULL, r2 = 0ULL, r3 = 0ULL;
            const float* p = rbase;
            #pragma unroll
            for (int s = 0; s < 8; ++s) {
                const ulonglong2 q0 = *reinterpret_cast<const ulonglong2*>(p);
                const ulonglong2 q1 = *reinterpret_cast<const ulonglong2*>(p + 4);
                fadd2(r0, q0.x); fadd2(r1, q0.y);
                fadd2(r2, q1.x); fadd2(r3, q1.y);
                p += 2 * 32 * 36;       // next k-split partner
            }
            float i0, i1, f0, f1, gg0, gg1, o0, o1;
            unpack2(r0, i0, i1); unpack2(r1, f0, f1);
            unpack2(r2, gg0, gg1); unpack2(r3, o0, o1);

            c0 = sigmoidf_acc(f0 + bf) * c0 + sigmoidf_acc(i0 + bi) * tanhf(gg0 + bg_);
            c1 = sigmoidf_acc(f1 + bf) * c1 + sigmoidf_acc(i1 + bi) * tanhf(gg1 + bg_);
            const float h0 = sigmoidf_acc(o0 + bo) * tanhf(c0);
            const float h1 = sigmoidf_acc(o1 + bo) * tanhf(c1);
            const int bG = gb0 + rbp * 2;
            st_cg(Hout + (size_t)bG * UNITS + rug, h0);
            st_cg(Hout + (size_t)(bG + 1) * UNITS + rug, h1);
        }

        group_sync(grp, ++nbar);   // H visible group-wide

        // ============ PHASE 2: heads + sample + output ============
        // stage h tile [32][260]
        for (int i = tid; i < 32 * 256; i += NTHR) {
            const int r = i >> 8, col = i & 255;
            S[r * 260 + col] = ld_cg(Hout + (size_t)(gb0 + r) * UNITS + col);
        }
        __syncthreads();

        ull acc = 0ULL;
        {
            const float* hr = S + pb * 260;
            const float* wr = W2 + prow * 260;
            #pragma unroll 4
            for (int k = 0; k < 256; k += 4) {
                const ulonglong2 hp = *reinterpret_cast<const ulonglong2*>(hr + k);
                const ulonglong2 wp = *reinterpret_cast<const ulonglong2*>(wr + k);
                ffma2(acc, hp.x, wp.x);
                ffma2(acc, hp.y, wp.y);
            }
        }
        float lo, hi; unpack2(acc, lo, hi);
        float val = lo + hi + bh;
        if (ph) val = fmaxf(val, 0.0f) + log1pf(expf(-fabsf(val))) + 1e-6f;

        const size_t ob = (size_t)pbg * (TST * DZ) + (size_t)t * DZ + pzc;
        if (ph) out[(size_t)BATCH * TST * DZ + ob] = val;
        else    out[ob] = val;

        if (ph) EX[pb * 8 + pj] = val;
        __syncthreads();
        if (!ph && t < TST - 1) {
            const float sg = EX[pb * 8 + pj];
            const float e  = __ldg(eps + (size_t)t * (BATCH * DZ)
                                       + (size_t)pbg * DZ + pzc);
            st_cg(g_Z + pbg * DZ + pzc, fmaf(sg, e, val));
        }

        group_sync(grp, ++nbar);   // z visible group-wide
    }

    // ---- reset barrier state for next graph replay (last-arriver protocol) ----
    if (tid == 0) {
        __threadfence();
        const unsigned d = atomicAdd(&g_done[grp * 32], 1u) + 1u;
        if (d == CPG) {
            g_cnt[grp * 32]  = 0;
            g_done[grp * 32] = 0;
            g_gen[grp * 32]  = 0;
            __threadfence();
        }
    }
}

extern "C" void kernel_launch(void* const* d_in, const int* in_sizes, int n_in,
                              void* d_out, int out_size) {
    (void)in_sizes; (void)n_in; (void)out_size;
    const float* inputs = (const float*)d_in[0];
    const float* Wk     = (const float*)d_in[1];
    const float* Wr     = (const float*)d_in[2];
    const float* bias   = (const float*)d_in[3];
    const float* Wmu    = (const float*)d_in[4];
    const float* bmu    = (const float*)d_in[5];
    const float* Wsg    = (const float*)d_in[6];
    const float* bsg    = (const float*)d_in[7];
    const float* eps    = (const float*)d_in[8];
    float* out          = (float*)d_out;

    const size_t smem_bytes = (size_t)SM_FLOATS * sizeof(float);  // 222464 B
    cudaFuncSetAttribute(fused_lstm_persistent,
                         cudaFuncAttributeMaxDynamicSharedMemorySize,
                         (int)smem_bytes);

    fused_lstm_persistent<<<NCTA, NTHR, smem_bytes>>>(
        inputs, Wk, Wr, bias, Wmu, bmu, Wsg, bsg, eps, out);
}